// round 14
// baseline (speedup 1.0000x reference)
#include <cuda_runtime.h>
#include <cuda_fp16.h>

#define N_NODES 100000
#define N_EDGES 1600000
#define D 128
#define ALPHA 0.5f
#define TILE_NODES 32
#define N_TILES (N_NODES / TILE_NODES)   // 3125 exact
#define NSTR 264
#define XSTR 132
#define SCAN_B 1024
#define SCAN_NB ((N_NODES + SCAN_B - 1) / SCAN_B)   // 98

// -------- static device scratch --------
__device__ __half g_y_src[(size_t)N_NODES * D];  // dinv_in[n] * (x @ (a*Ws)^T)[n]
__device__ __half g_y_dst[(size_t)N_NODES * D];  // dinv_out[n] * (x @ ((1-a)*Wd)^T)[n]
__device__ int   g_cnt_row[N_NODES], g_cnt_col[N_NODES];
__device__ int   g_off_row[N_NODES], g_off_col[N_NODES];
__device__ int   g_cur_row[N_NODES], g_cur_col[N_NODES];
__device__ int   g_part_row[SCAN_NB], g_part_col[SCAN_NB];
__device__ float g_dinv_out[N_NODES], g_dinv_in[N_NODES];
__device__ int   g_sorted_col[N_EDGES];
__device__ int   g_sorted_row[N_EDGES];
__device__ int   g_is64;

__device__ __forceinline__ void cp_async16(void* smem_dst, const void* gsrc) {
  unsigned sa = (unsigned)__cvta_generic_to_shared(smem_dst);
  asm volatile("cp.async.ca.shared.global [%0], [%1], 16;" :: "r"(sa), "l"(gsrc));
}
__device__ __forceinline__ unsigned f2tf32(float f) {
  unsigned t; asm("cvt.rna.tf32.f32 %0, %1;" : "=r"(t) : "f"(f));
  return t;
}
__device__ __forceinline__ void mma_tf32(float* c, unsigned a0, unsigned a1,
                                         unsigned a2, unsigned a3,
                                         unsigned b0, unsigned b1) {
  asm volatile(
    "mma.sync.aligned.m16n8k8.row.col.f32.tf32.tf32.f32 "
    "{%0,%1,%2,%3}, {%4,%5,%6,%7}, {%8,%9}, {%0,%1,%2,%3};"
    : "+f"(c[0]), "+f"(c[1]), "+f"(c[2]), "+f"(c[3])
    : "r"(a0), "r"(a1), "r"(a2), "r"(a3), "r"(b0), "r"(b1));
}

// -------- 1: zero counts + detect index dtype --------
__global__ void k_prep(const void* ei) {
  long long i = (long long)blockIdx.x * blockDim.x + threadIdx.x;
  if (i == 0) {
    const long long* p = (const long long*)ei;
    int ok = 1;
#pragma unroll
    for (int j = 0; j < 16; j++) {
      long long v = p[j];
      if (v < 0 || v >= N_NODES) ok = 0;
    }
    g_is64 = ok;
  }
  if (i < N_NODES) { g_cnt_row[i] = 0; g_cnt_col[i] = 0; }
}

// -------- 2: degree histograms, 2 edges/thread --------
__global__ void k_hist(const void* ei) {
  long long t = (long long)blockIdx.x * blockDim.x + threadIdx.x;
  if (t >= N_EDGES / 2) return;
  int r0, r1, c0, c1;
  if (g_is64) {
    longlong2 rr = ((const longlong2*)ei)[t];
    longlong2 cc = ((const longlong2*)((const long long*)ei + N_EDGES))[t];
    r0 = (int)rr.x; r1 = (int)rr.y; c0 = (int)cc.x; c1 = (int)cc.y;
  } else {
    int2 rr = ((const int2*)ei)[t];
    int2 cc = ((const int2*)((const int*)ei + N_EDGES))[t];
    r0 = rr.x; r1 = rr.y; c0 = cc.x; c1 = cc.y;
  }
  atomicAdd(&g_cnt_row[r0], 1); atomicAdd(&g_cnt_row[r1], 1);
  atomicAdd(&g_cnt_col[c0], 1); atomicAdd(&g_cnt_col[c1], 1);
}

// -------- B: blockwise scan; cursors; dinv --------
__global__ void k_scan_blocks() {
  __shared__ int sh[SCAN_B];
  int b = blockIdx.x, t = threadIdx.x;
  int gi = b * SCAN_B + t;

  int v = (gi < N_NODES) ? g_cnt_row[gi] : 0;
  sh[t] = v; __syncthreads();
  for (int o = 1; o < SCAN_B; o <<= 1) {
    int x = (t >= o) ? sh[t - o] : 0;
    __syncthreads(); sh[t] += x; __syncthreads();
  }
  if (gi < N_NODES) {
    g_off_row[gi] = sh[t] - v; g_cur_row[gi] = sh[t] - v;
    g_dinv_out[gi] = v > 0 ? rsqrtf((float)v) : 0.f;
  }
  if (t == SCAN_B - 1) g_part_row[b] = sh[t];
  __syncthreads();

  v = (gi < N_NODES) ? g_cnt_col[gi] : 0;
  sh[t] = v; __syncthreads();
  for (int o = 1; o < SCAN_B; o <<= 1) {
    int x = (t >= o) ? sh[t - o] : 0;
    __syncthreads(); sh[t] += x; __syncthreads();
  }
  if (gi < N_NODES) {
    g_off_col[gi] = sh[t] - v; g_cur_col[gi] = sh[t] - v;
    g_dinv_in[gi] = v > 0 ? rsqrtf((float)v) : 0.f;
  }
  if (t == SCAN_B - 1) g_part_col[b] = sh[t];
}

__global__ void k_scan_tops() {
  __shared__ int sh[128];
  int t = threadIdx.x;
  int v = (t < SCAN_NB) ? g_part_row[t] : 0;
  sh[t] = v; __syncthreads();
  for (int o = 1; o < 128; o <<= 1) {
    int x = (t >= o) ? sh[t - o] : 0;
    __syncthreads(); sh[t] += x; __syncthreads();
  }
  if (t < SCAN_NB) g_part_row[t] = sh[t] - v;
  __syncthreads();
  v = (t < SCAN_NB) ? g_part_col[t] : 0;
  sh[t] = v; __syncthreads();
  for (int o = 1; o < 128; o <<= 1) {
    int x = (t >= o) ? sh[t - o] : 0;
    __syncthreads(); sh[t] += x; __syncthreads();
  }
  if (t < SCAN_NB) g_part_col[t] = sh[t] - v;
}

// -------- build CSR, 2 edges/thread --------
__global__ void k_build(const void* ei) {
  long long t = (long long)blockIdx.x * blockDim.x + threadIdx.x;
  if (t >= N_EDGES / 2) return;
  int r0, r1, c0, c1;
  if (g_is64) {
    longlong2 rr = ((const longlong2*)ei)[t];
    longlong2 cc = ((const longlong2*)((const long long*)ei + N_EDGES))[t];
    r0 = (int)rr.x; r1 = (int)rr.y; c0 = (int)cc.x; c1 = (int)cc.y;
  } else {
    int2 rr = ((const int2*)ei)[t];
    int2 cc = ((const int2*)((const int*)ei + N_EDGES))[t];
    r0 = rr.x; r1 = rr.y; c0 = cc.x; c1 = cc.y;
  }
  int p0 = atomicAdd(&g_cur_row[r0], 1) + g_part_row[r0 >> 10];
  g_sorted_col[p0] = c0;
  int p1 = atomicAdd(&g_cur_row[r1], 1) + g_part_row[r1 >> 10];
  g_sorted_col[p1] = c1;
  int q0 = atomicAdd(&g_cur_col[c0], 1) + g_part_col[c0 >> 10];
  g_sorted_row[q0] = r0;
  int q1 = atomicAdd(&g_cur_col[c1], 1) + g_part_col[c1 >> 10];
  g_sorted_row[q1] = r1;
}

// -------- transform: tf32 mma, fp16 prescaled y (unchanged from R13) --------
__global__ void __launch_bounds__(256, 1) k_transform(
    const float* __restrict__ x,
    const float* __restrict__ W_src,
    const float* __restrict__ W_dst) {
  extern __shared__ float smem[];
  float* Wsm = smem;
  float* xs0 = Wsm + 128 * NSTR;
  float* xs1 = xs0 + TILE_NODES * XSTR;

  int tid = threadIdx.x;
  for (int idx = tid; idx < 128 * 256; idx += 256) {
    int k = idx >> 8, n = idx & 255;
    float w = (n < 128) ? ALPHA * W_src[n * 128 + k]
                        : (1.f - ALPHA) * W_dst[(n - 128) * 128 + k];
    Wsm[k * NSTR + n] = __uint_as_float(f2tf32(w));
  }

  int lane = tid & 31, wid = tid >> 5;
  int g = lane >> 2, tig = lane & 3;
  int wm = wid & 1, wn = wid >> 1;

  {
    long long base = (long long)blockIdx.x * TILE_NODES;
    for (int i = tid; i < TILE_NODES * 32; i += 256) {
      int row = i >> 5, ch = i & 31;
      cp_async16(xs0 + row * XSTR + ch * 4, x + (base + row) * D + ch * 4);
    }
    asm volatile("cp.async.commit_group;");
  }

  int pp = 0;
  for (int tile = blockIdx.x; tile < N_TILES; tile += gridDim.x) {
    long long base = (long long)tile * TILE_NODES;
    float* xsr = pp ? xs1 : xs0;
    float* xsw = pp ? xs0 : xs1;

    asm volatile("cp.async.wait_group 0;");
    __syncthreads();

    int next = tile + gridDim.x;
    if (next < N_TILES) {
      long long nb = (long long)next * TILE_NODES;
      for (int i = tid; i < TILE_NODES * 32; i += 256) {
        int row = i >> 5, ch = i & 31;
        cp_async16(xsw + row * XSTR + ch * 4, x + (nb + row) * D + ch * 4);
      }
      asm volatile("cp.async.commit_group;");
    }

    float c[8][4];
#pragma unroll
    for (int nt = 0; nt < 8; nt++) { c[nt][0]=0.f; c[nt][1]=0.f; c[nt][2]=0.f; c[nt][3]=0.f; }

#pragma unroll
    for (int ks = 0; ks < 16; ks++) {
      int k0 = ks * 8;
      const float* ab = xsr + (wm * 16 + g) * XSTR + k0 + tig;
      unsigned a0 = f2tf32(ab[0]);
      unsigned a1 = f2tf32(ab[8 * XSTR]);
      unsigned a2 = f2tf32(ab[4]);
      unsigned a3 = f2tf32(ab[8 * XSTR + 4]);
      const float* bb = Wsm + (k0 + tig) * NSTR + wn * 64 + g;
#pragma unroll
      for (int nt = 0; nt < 8; nt++) {
        unsigned b0 = __float_as_uint(bb[nt * 8]);
        unsigned b1 = __float_as_uint(bb[nt * 8 + 4 * NSTR]);
        mma_tf32(c[nt], a0, a1, a2, a3, b0, b1);
      }
    }

    {
      int r0 = wm * 16 + g, r1 = r0 + 8;
      long long n0 = base + r0, n1 = base + r1;
      float s0, s1;
      __half* ybase;
      if (wn < 2) {
        int c0 = g_cnt_col[n0], c1 = g_cnt_col[n1];
        s0 = c0 > 0 ? rsqrtf((float)c0) : 0.f;
        s1 = c1 > 0 ? rsqrtf((float)c1) : 0.f;
        ybase = g_y_src;
      } else {
        int c0 = g_cnt_row[n0], c1 = g_cnt_row[n1];
        s0 = c0 > 0 ? rsqrtf((float)c0) : 0.f;
        s1 = c1 > 0 ? rsqrtf((float)c1) : 0.f;
        ybase = g_y_dst;
      }
      int cb = (wn & 1) * 64 + tig * 2;
#pragma unroll
      for (int nt = 0; nt < 8; nt++) {
        __half2 h0 = __floats2half2_rn(s0 * c[nt][0], s0 * c[nt][1]);
        *(__half2*)(ybase + n0 * D + cb + nt * 8) = h0;
        __half2 h1 = __floats2half2_rn(s1 * c[nt][2], s1 * c[nt][3]);
        *(__half2*)(ybase + n1 * D + cb + nt * 8) = h1;
      }
    }
    pp ^= 1;
  }
}

// -------- gather: warp/node, HALF-WARP rows (16 lanes x uint4 = 256B) --------
__device__ __forceinline__ void acc8(float* a, uint4 v) {
  float2 p0 = __half22float2(*(const __half2*)&v.x);
  float2 p1 = __half22float2(*(const __half2*)&v.y);
  float2 p2 = __half22float2(*(const __half2*)&v.z);
  float2 p3 = __half22float2(*(const __half2*)&v.w);
  a[0] += p0.x; a[1] += p0.y; a[2] += p1.x; a[3] += p1.y;
  a[4] += p2.x; a[5] += p2.y; a[6] += p3.x; a[7] += p3.y;
}

__global__ void __launch_bounds__(256, 2) k_gather(
    float* __restrict__ out,
    const float* __restrict__ b_src, const float* __restrict__ b_dst) {
  int lane = threadIdx.x & 31;
  int h = lane >> 4;          // half-warp id: splits neighbor list even/odd
  int hl = lane & 15;         // lane within half: owns cols [hl*8, hl*8+8)
  int node = (blockIdx.x * blockDim.x + threadIdx.x) >> 5;
  if (node >= N_NODES) return;

  float accf[8], accb[8];
#pragma unroll
  for (int k = 0; k < 8; k++) { accf[k] = 0.f; accb[k] = 0.f; }
  const unsigned FULL = 0xffffffffu;
  const uint4* ysrc = (const uint4*)g_y_src;   // row = node*16 uint4
  const uint4* ydst = (const uint4*)g_y_dst;

  // fwd: sum y_src'[c] over out-neighbors
  {
    int s = g_off_row[node] + g_part_row[node >> 10];
    int cnt = g_cnt_row[node];
    for (int bse = 0; bse < cnt; bse += 32) {
      int n = min(32, cnt - bse);
      int idx = (lane < n) ? g_sorted_col[s + bse + lane] : 0;
      int j = 0;
      for (; j + 8 <= n; j += 8) {     // halves take j+h, j+h+2, j+h+4, j+h+6
        int i0 = __shfl_sync(FULL, idx, j + h);
        int i1 = __shfl_sync(FULL, idx, j + h + 2);
        int i2 = __shfl_sync(FULL, idx, j + h + 4);
        int i3 = __shfl_sync(FULL, idx, j + h + 6);
        uint4 v0 = ysrc[(long long)i0 * 16 + hl];
        uint4 v1 = ysrc[(long long)i1 * 16 + hl];
        uint4 v2 = ysrc[(long long)i2 * 16 + hl];
        uint4 v3 = ysrc[(long long)i3 * 16 + hl];
        acc8(accf, v0); acc8(accf, v1); acc8(accf, v2); acc8(accf, v3);
      }
      for (; j + 2 <= n; j += 2) {     // pair: half h takes j+h
        int i0 = __shfl_sync(FULL, idx, j + h);
        uint4 v0 = ysrc[(long long)i0 * 16 + hl];
        acc8(accf, v0);
      }
      if (j < n) {                     // single leftover: half 0 only
        int i0 = __shfl_sync(FULL, idx, j);
        if (h == 0) { uint4 v0 = ysrc[(long long)i0 * 16 + hl]; acc8(accf, v0); }
      }
    }
  }
  // bwd: sum y_dst'[r] over in-neighbors
  {
    int s = g_off_col[node] + g_part_col[node >> 10];
    int cnt = g_cnt_col[node];
    for (int bse = 0; bse < cnt; bse += 32) {
      int n = min(32, cnt - bse);
      int idx = (lane < n) ? g_sorted_row[s + bse + lane] : 0;
      int j = 0;
      for (; j + 8 <= n; j += 8) {
        int i0 = __shfl_sync(FULL, idx, j + h);
        int i1 = __shfl_sync(FULL, idx, j + h + 2);
        int i2 = __shfl_sync(FULL, idx, j + h + 4);
        int i3 = __shfl_sync(FULL, idx, j + h + 6);
        uint4 v0 = ydst[(long long)i0 * 16 + hl];
        uint4 v1 = ydst[(long long)i1 * 16 + hl];
        uint4 v2 = ydst[(long long)i2 * 16 + hl];
        uint4 v3 = ydst[(long long)i3 * 16 + hl];
        acc8(accb, v0); acc8(accb, v1); acc8(accb, v2); acc8(accb, v3);
      }
      for (; j + 2 <= n; j += 2) {
        int i0 = __shfl_sync(FULL, idx, j + h);
        uint4 v0 = ydst[(long long)i0 * 16 + hl];
        acc8(accb, v0);
      }
      if (j < n) {
        int i0 = __shfl_sync(FULL, idx, j);
        if (h == 0) { uint4 v0 = ydst[(long long)i0 * 16 + hl]; acc8(accb, v0); }
      }
    }
  }

  // combine the two halves
#pragma unroll
  for (int k = 0; k < 8; k++) {
    accf[k] += __shfl_xor_sync(FULL, accf[k], 16);
    accb[k] += __shfl_xor_sync(FULL, accb[k], 16);
  }

  if (h == 0) {
    float dout = g_dinv_out[node];
    float di   = g_dinv_in[node];
    float o[8];
#pragma unroll
    for (int k = 0; k < 8; k++) {
      int bi = hl * 8 + k;
      o[k] = ALPHA * b_src[bi] + (1.f - ALPHA) * b_dst[bi]
           + dout * accf[k] + di * accb[k];
    }
    float4* po = (float4*)(out + (long long)node * D + hl * 8);
    po[0] = make_float4(o[0], o[1], o[2], o[3]);
    po[1] = make_float4(o[4], o[5], o[6], o[7]);
  }
}

// -------- launch: R11 fork-join topology --------
extern "C" void kernel_launch(void* const* d_in, const int* in_sizes, int n_in,
                              void* d_out, int out_size) {
  const float* x     = (const float*)d_in[0];
  const void*  ei    = d_in[1];
  const float* W_src = (const float*)d_in[2];
  const float* b_src = (const float*)d_in[3];
  const float* W_dst = (const float*)d_in[4];
  const float* b_dst = (const float*)d_in[5];
  float* out = (float*)d_out;

  cudaStream_t s2;
  cudaStreamCreateWithFlags(&s2, cudaStreamNonBlocking);
  cudaEvent_t evFork, evJoin;
  cudaEventCreateWithFlags(&evFork, cudaEventDisableTiming);
  cudaEventCreateWithFlags(&evJoin, cudaEventDisableTiming);

  k_prep<<<(N_NODES + 255) / 256, 256>>>(ei);
  k_hist<<<(N_EDGES / 2 + 255) / 256, 256>>>(ei);

  cudaEventRecord(evFork, 0);
  cudaStreamWaitEvent(s2, evFork, 0);
  k_scan_blocks<<<SCAN_NB, SCAN_B, 0, s2>>>();
  k_scan_tops<<<1, 128, 0, s2>>>();
  k_build<<<(N_EDGES / 2 + 255) / 256, 256, 0, s2>>>(ei);
  cudaEventRecord(evJoin, s2);

  size_t smem_bytes = (size_t)(128 * NSTR + 2 * TILE_NODES * XSTR) * sizeof(float);
  cudaFuncSetAttribute(k_transform, cudaFuncAttributeMaxDynamicSharedMemorySize,
                       (int)smem_bytes);
  k_transform<<<152, 256, smem_bytes>>>(x, W_src, W_dst);

  cudaStreamWaitEvent(0, evJoin, 0);
  k_gather<<<(N_NODES * 32 + 255) / 256, 256>>>(out, b_src, b_dst);
}

// round 15
// speedup vs baseline: 1.1224x; 1.1224x over previous
#include <cuda_runtime.h>
#include <cuda_fp16.h>

#define N_NODES 100000
#define N_EDGES 1600000
#define D 128
#define ALPHA 0.5f
#define TILE_NODES 32
#define N_TILES (N_NODES / TILE_NODES)   // 3125 exact
#define NSTR 264
#define XSTR 132
#define SCAN_B 1024
#define SCAN_NB ((N_NODES + SCAN_B - 1) / SCAN_B)   // 98

// -------- static device scratch (zero-initialized at module load) --------
__device__ __half g_y_src[(size_t)N_NODES * D];  // dinv_in[n] * (x @ (a*Ws)^T)[n]
__device__ __half g_y_dst[(size_t)N_NODES * D];  // dinv_out[n] * (x @ ((1-a)*Wd)^T)[n]
__device__ int   g_cnt_row[N_NODES], g_cnt_col[N_NODES];   // ALWAYS zero at call entry
__device__ int   g_off_row[N_NODES], g_off_col[N_NODES];
__device__ int   g_cur_row[N_NODES], g_cur_col[N_NODES];
__device__ int   g_part_row[SCAN_NB], g_part_col[SCAN_NB];
__device__ float g_dinv_out[N_NODES], g_dinv_in[N_NODES];
__device__ int   g_sorted_col[N_EDGES];
__device__ int   g_sorted_row[N_EDGES];
__device__ int   g_is64;

__device__ __forceinline__ void cp_async16(void* smem_dst, const void* gsrc) {
  unsigned sa = (unsigned)__cvta_generic_to_shared(smem_dst);
  asm volatile("cp.async.ca.shared.global [%0], [%1], 16;" :: "r"(sa), "l"(gsrc));
}
__device__ __forceinline__ unsigned f2tf32(float f) {
  unsigned t; asm("cvt.rna.tf32.f32 %0, %1;" : "=r"(t) : "f"(f));
  return t;
}
__device__ __forceinline__ void mma_tf32(float* c, unsigned a0, unsigned a1,
                                         unsigned a2, unsigned a3,
                                         unsigned b0, unsigned b1) {
  asm volatile(
    "mma.sync.aligned.m16n8k8.row.col.f32.tf32.tf32.f32 "
    "{%0,%1,%2,%3}, {%4,%5,%6,%7}, {%8,%9}, {%0,%1,%2,%3};"
    : "+f"(c[0]), "+f"(c[1]), "+f"(c[2]), "+f"(c[3])
    : "r"(a0), "r"(a1), "r"(a2), "r"(a3), "r"(b0), "r"(b1));
}

// -------- 0: dtype detect only (counts are pre-zeroed; see k_clear) --------
__global__ void k_detect(const void* ei) {
  if (threadIdx.x == 0) {
    const long long* p = (const long long*)ei;
    int ok = 1;
#pragma unroll
    for (int j = 0; j < 16; j++) {
      long long v = p[j];
      if (v < 0 || v >= N_NODES) ok = 0;
    }
    g_is64 = ok;   // int32 data read as int64 is out of range w.p. ~1
  }
}

// -------- tail: re-zero counts for the next (graph-replayed) call --------
__global__ void k_clear() {
  int i = blockIdx.x * blockDim.x + threadIdx.x;
  if (i < N_NODES) { g_cnt_row[i] = 0; g_cnt_col[i] = 0; }
}

// -------- 1: degree histograms, 2 edges/thread --------
__global__ void k_hist(const void* ei) {
  long long t = (long long)blockIdx.x * blockDim.x + threadIdx.x;
  if (t >= N_EDGES / 2) return;
  int r0, r1, c0, c1;
  if (g_is64) {
    longlong2 rr = ((const longlong2*)ei)[t];
    longlong2 cc = ((const longlong2*)((const long long*)ei + N_EDGES))[t];
    r0 = (int)rr.x; r1 = (int)rr.y; c0 = (int)cc.x; c1 = (int)cc.y;
  } else {
    int2 rr = ((const int2*)ei)[t];
    int2 cc = ((const int2*)((const int*)ei + N_EDGES))[t];
    r0 = rr.x; r1 = rr.y; c0 = cc.x; c1 = cc.y;
  }
  atomicAdd(&g_cnt_row[r0], 1); atomicAdd(&g_cnt_row[r1], 1);
  atomicAdd(&g_cnt_col[c0], 1); atomicAdd(&g_cnt_col[c1], 1);
}

// -------- B: blockwise scan; cursors; dinv (stream 2) --------
__global__ void k_scan_blocks() {
  __shared__ int sh[SCAN_B];
  int b = blockIdx.x, t = threadIdx.x;
  int gi = b * SCAN_B + t;

  int v = (gi < N_NODES) ? g_cnt_row[gi] : 0;
  sh[t] = v; __syncthreads();
  for (int o = 1; o < SCAN_B; o <<= 1) {
    int x = (t >= o) ? sh[t - o] : 0;
    __syncthreads(); sh[t] += x; __syncthreads();
  }
  if (gi < N_NODES) {
    g_off_row[gi] = sh[t] - v; g_cur_row[gi] = sh[t] - v;
    g_dinv_out[gi] = v > 0 ? rsqrtf((float)v) : 0.f;
  }
  if (t == SCAN_B - 1) g_part_row[b] = sh[t];
  __syncthreads();

  v = (gi < N_NODES) ? g_cnt_col[gi] : 0;
  sh[t] = v; __syncthreads();
  for (int o = 1; o < SCAN_B; o <<= 1) {
    int x = (t >= o) ? sh[t - o] : 0;
    __syncthreads(); sh[t] += x; __syncthreads();
  }
  if (gi < N_NODES) {
    g_off_col[gi] = sh[t] - v; g_cur_col[gi] = sh[t] - v;
    g_dinv_in[gi] = v > 0 ? rsqrtf((float)v) : 0.f;
  }
  if (t == SCAN_B - 1) g_part_col[b] = sh[t];
}

__global__ void k_scan_tops() {
  __shared__ int sh[128];
  int t = threadIdx.x;
  int v = (t < SCAN_NB) ? g_part_row[t] : 0;
  sh[t] = v; __syncthreads();
  for (int o = 1; o < 128; o <<= 1) {
    int x = (t >= o) ? sh[t - o] : 0;
    __syncthreads(); sh[t] += x; __syncthreads();
  }
  if (t < SCAN_NB) g_part_row[t] = sh[t] - v;
  __syncthreads();
  v = (t < SCAN_NB) ? g_part_col[t] : 0;
  sh[t] = v; __syncthreads();
  for (int o = 1; o < 128; o <<= 1) {
    int x = (t >= o) ? sh[t - o] : 0;
    __syncthreads(); sh[t] += x; __syncthreads();
  }
  if (t < SCAN_NB) g_part_col[t] = sh[t] - v;
}

// -------- build CSR, 2 edges/thread --------
__global__ void k_build(const void* ei) {
  long long t = (long long)blockIdx.x * blockDim.x + threadIdx.x;
  if (t >= N_EDGES / 2) return;
  int r0, r1, c0, c1;
  if (g_is64) {
    longlong2 rr = ((const longlong2*)ei)[t];
    longlong2 cc = ((const longlong2*)((const long long*)ei + N_EDGES))[t];
    r0 = (int)rr.x; r1 = (int)rr.y; c0 = (int)cc.x; c1 = (int)cc.y;
  } else {
    int2 rr = ((const int2*)ei)[t];
    int2 cc = ((const int2*)((const int*)ei + N_EDGES))[t];
    r0 = rr.x; r1 = rr.y; c0 = cc.x; c1 = cc.y;
  }
  int p0 = atomicAdd(&g_cur_row[r0], 1) + g_part_row[r0 >> 10];
  g_sorted_col[p0] = c0;
  int p1 = atomicAdd(&g_cur_row[r1], 1) + g_part_row[r1 >> 10];
  g_sorted_col[p1] = c1;
  int q0 = atomicAdd(&g_cur_col[c0], 1) + g_part_col[c0 >> 10];
  g_sorted_row[q0] = r0;
  int q1 = atomicAdd(&g_cur_col[c1], 1) + g_part_col[c1 >> 10];
  g_sorted_row[q1] = r1;
}

// -------- transform: tf32 mma, fp16 prescaled y (R13, frozen) --------
__global__ void __launch_bounds__(256, 1) k_transform(
    const float* __restrict__ x,
    const float* __restrict__ W_src,
    const float* __restrict__ W_dst) {
  extern __shared__ float smem[];
  float* Wsm = smem;
  float* xs0 = Wsm + 128 * NSTR;
  float* xs1 = xs0 + TILE_NODES * XSTR;

  int tid = threadIdx.x;
  for (int idx = tid; idx < 128 * 256; idx += 256) {
    int k = idx >> 8, n = idx & 255;
    float w = (n < 128) ? ALPHA * W_src[n * 128 + k]
                        : (1.f - ALPHA) * W_dst[(n - 128) * 128 + k];
    Wsm[k * NSTR + n] = __uint_as_float(f2tf32(w));
  }

  int lane = tid & 31, wid = tid >> 5;
  int g = lane >> 2, tig = lane & 3;
  int wm = wid & 1, wn = wid >> 1;

  {
    long long base = (long long)blockIdx.x * TILE_NODES;
    for (int i = tid; i < TILE_NODES * 32; i += 256) {
      int row = i >> 5, ch = i & 31;
      cp_async16(xs0 + row * XSTR + ch * 4, x + (base + row) * D + ch * 4);
    }
    asm volatile("cp.async.commit_group;");
  }

  int pp = 0;
  for (int tile = blockIdx.x; tile < N_TILES; tile += gridDim.x) {
    long long base = (long long)tile * TILE_NODES;
    float* xsr = pp ? xs1 : xs0;
    float* xsw = pp ? xs0 : xs1;

    asm volatile("cp.async.wait_group 0;");
    __syncthreads();

    int next = tile + gridDim.x;
    if (next < N_TILES) {
      long long nb = (long long)next * TILE_NODES;
      for (int i = tid; i < TILE_NODES * 32; i += 256) {
        int row = i >> 5, ch = i & 31;
        cp_async16(xsw + row * XSTR + ch * 4, x + (nb + row) * D + ch * 4);
      }
      asm volatile("cp.async.commit_group;");
    }

    float c[8][4];
#pragma unroll
    for (int nt = 0; nt < 8; nt++) { c[nt][0]=0.f; c[nt][1]=0.f; c[nt][2]=0.f; c[nt][3]=0.f; }

#pragma unroll
    for (int ks = 0; ks < 16; ks++) {
      int k0 = ks * 8;
      const float* ab = xsr + (wm * 16 + g) * XSTR + k0 + tig;
      unsigned a0 = f2tf32(ab[0]);
      unsigned a1 = f2tf32(ab[8 * XSTR]);
      unsigned a2 = f2tf32(ab[4]);
      unsigned a3 = f2tf32(ab[8 * XSTR + 4]);
      const float* bb = Wsm + (k0 + tig) * NSTR + wn * 64 + g;
#pragma unroll
      for (int nt = 0; nt < 8; nt++) {
        unsigned b0 = __float_as_uint(bb[nt * 8]);
        unsigned b1 = __float_as_uint(bb[nt * 8 + 4 * NSTR]);
        mma_tf32(c[nt], a0, a1, a2, a3, b0, b1);
      }
    }

    {
      int r0 = wm * 16 + g, r1 = r0 + 8;
      long long n0 = base + r0, n1 = base + r1;
      float s0, s1;
      __half* ybase;
      if (wn < 2) {
        int c0 = g_cnt_col[n0], c1 = g_cnt_col[n1];
        s0 = c0 > 0 ? rsqrtf((float)c0) : 0.f;
        s1 = c1 > 0 ? rsqrtf((float)c1) : 0.f;
        ybase = g_y_src;
      } else {
        int c0 = g_cnt_row[n0], c1 = g_cnt_row[n1];
        s0 = c0 > 0 ? rsqrtf((float)c0) : 0.f;
        s1 = c1 > 0 ? rsqrtf((float)c1) : 0.f;
        ybase = g_y_dst;
      }
      int cb = (wn & 1) * 64 + tig * 2;
#pragma unroll
      for (int nt = 0; nt < 8; nt++) {
        __half2 h0 = __floats2half2_rn(s0 * c[nt][0], s0 * c[nt][1]);
        *(__half2*)(ybase + n0 * D + cb + nt * 8) = h0;
        __half2 h1 = __floats2half2_rn(s1 * c[nt][2], s1 * c[nt][3]);
        *(__half2*)(ybase + n1 * D + cb + nt * 8) = h1;
      }
    }
    pp ^= 1;
  }
}

// -------- gather: warp/node, uint2 rows, 4-way MLP (R13, proven) --------
__device__ __forceinline__ void acc_row(float4& acc, const uint2 v) {
  float2 v0 = __half22float2(*(const __half2*)&v.x);
  float2 v1 = __half22float2(*(const __half2*)&v.y);
  acc.x += v0.x; acc.y += v0.y; acc.z += v1.x; acc.w += v1.y;
}

__global__ void __launch_bounds__(256, 4) k_gather(
    float* __restrict__ out,
    const float* __restrict__ b_src, const float* __restrict__ b_dst) {
  int lane = threadIdx.x & 31;
  int node = (blockIdx.x * blockDim.x + threadIdx.x) >> 5;
  if (node >= N_NODES) return;

  float4 accf = make_float4(0.f, 0.f, 0.f, 0.f);
  float4 accb = make_float4(0.f, 0.f, 0.f, 0.f);
  const unsigned FULL = 0xffffffffu;

  {
    int s = g_off_row[node] + g_part_row[node >> 10];
    int cnt = g_cnt_row[node];
    for (int bse = 0; bse < cnt; bse += 32) {
      int n = min(32, cnt - bse);
      int idx = (lane < n) ? g_sorted_col[s + bse + lane] : 0;
      int j = 0;
      for (; j + 4 <= n; j += 4) {
        int i0 = __shfl_sync(FULL, idx, j);
        int i1 = __shfl_sync(FULL, idx, j + 1);
        int i2 = __shfl_sync(FULL, idx, j + 2);
        int i3 = __shfl_sync(FULL, idx, j + 3);
        uint2 v0 = ((const uint2*)g_y_src)[(long long)i0 * 32 + lane];
        uint2 v1 = ((const uint2*)g_y_src)[(long long)i1 * 32 + lane];
        uint2 v2 = ((const uint2*)g_y_src)[(long long)i2 * 32 + lane];
        uint2 v3 = ((const uint2*)g_y_src)[(long long)i3 * 32 + lane];
        acc_row(accf, v0); acc_row(accf, v1); acc_row(accf, v2); acc_row(accf, v3);
      }
      for (; j < n; j++) {
        int i0 = __shfl_sync(FULL, idx, j);
        uint2 v0 = ((const uint2*)g_y_src)[(long long)i0 * 32 + lane];
        acc_row(accf, v0);
      }
    }
  }
  {
    int s = g_off_col[node] + g_part_col[node >> 10];
    int cnt = g_cnt_col[node];
    for (int bse = 0; bse < cnt; bse += 32) {
      int n = min(32, cnt - bse);
      int idx = (lane < n) ? g_sorted_row[s + bse + lane] : 0;
      int j = 0;
      for (; j + 4 <= n; j += 4) {
        int i0 = __shfl_sync(FULL, idx, j);
        int i1 = __shfl_sync(FULL, idx, j + 1);
        int i2 = __shfl_sync(FULL, idx, j + 2);
        int i3 = __shfl_sync(FULL, idx, j + 3);
        uint2 v0 = ((const uint2*)g_y_dst)[(long long)i0 * 32 + lane];
        uint2 v1 = ((const uint2*)g_y_dst)[(long long)i1 * 32 + lane];
        uint2 v2 = ((const uint2*)g_y_dst)[(long long)i2 * 32 + lane];
        uint2 v3 = ((const uint2*)g_y_dst)[(long long)i3 * 32 + lane];
        acc_row(accb, v0); acc_row(accb, v1); acc_row(accb, v2); acc_row(accb, v3);
      }
      for (; j < n; j++) {
        int i0 = __shfl_sync(FULL, idx, j);
        uint2 v0 = ((const uint2*)g_y_dst)[(long long)i0 * 32 + lane];
        acc_row(accb, v0);
      }
    }
  }

  float dout = g_dinv_out[node];
  float di   = g_dinv_in[node];
  int bidx = lane * 4;
  float4 o;
  o.x = ALPHA * b_src[bidx+0] + (1.f-ALPHA) * b_dst[bidx+0] + dout * accf.x + di * accb.x;
  o.y = ALPHA * b_src[bidx+1] + (1.f-ALPHA) * b_dst[bidx+1] + dout * accf.y + di * accb.y;
  o.z = ALPHA * b_src[bidx+2] + (1.f-ALPHA) * b_dst[bidx+2] + dout * accf.z + di * accb.z;
  o.w = ALPHA * b_src[bidx+3] + (1.f-ALPHA) * b_dst[bidx+3] + dout * accf.w + di * accb.w;
  ((float4*)(out + (long long)node * D))[lane] = o;
}

// -------- launch: fork-join; trailing clear restores count invariant --------
extern "C" void kernel_launch(void* const* d_in, const int* in_sizes, int n_in,
                              void* d_out, int out_size) {
  const float* x     = (const float*)d_in[0];
  const void*  ei    = d_in[1];
  const float* W_src = (const float*)d_in[2];
  const float* b_src = (const float*)d_in[3];
  const float* W_dst = (const float*)d_in[4];
  const float* b_dst = (const float*)d_in[5];
  float* out = (float*)d_out;

  cudaStream_t s2;
  cudaStreamCreateWithFlags(&s2, cudaStreamNonBlocking);
  cudaEvent_t evFork, evJoin;
  cudaEventCreateWithFlags(&evFork, cudaEventDisableTiming);
  cudaEventCreateWithFlags(&evJoin, cudaEventDisableTiming);

  k_detect<<<1, 32>>>(ei);
  k_hist<<<(N_EDGES / 2 + 255) / 256, 256>>>(ei);

  cudaEventRecord(evFork, 0);
  cudaStreamWaitEvent(s2, evFork, 0);
  k_scan_blocks<<<SCAN_NB, SCAN_B, 0, s2>>>();
  k_scan_tops<<<1, 128, 0, s2>>>();
  k_build<<<(N_EDGES / 2 + 255) / 256, 256, 0, s2>>>(ei);
  cudaEventRecord(evJoin, s2);

  size_t smem_bytes = (size_t)(128 * NSTR + 2 * TILE_NODES * XSTR) * sizeof(float);
  cudaFuncSetAttribute(k_transform, cudaFuncAttributeMaxDynamicSharedMemorySize,
                       (int)smem_bytes);
  k_transform<<<152, 256, smem_bytes>>>(x, W_src, W_dst);

  cudaStreamWaitEvent(0, evJoin, 0);
  k_gather<<<(N_NODES * 32 + 255) / 256, 256>>>(out, b_src, b_dst);
  k_clear<<<(N_NODES + 255) / 256, 256>>>();   // counts zeroed for next replay
}

// round 16
// speedup vs baseline: 1.2357x; 1.1010x over previous
#include <cuda_runtime.h>
#include <cuda_fp16.h>

#define N_NODES 100000
#define N_EDGES 1600000
#define D 128
#define ALPHA 0.5f
#define TILE_NODES 32
#define N_TILES (N_NODES / TILE_NODES)   // 3125 exact
#define NSTR 264
#define XSTR 132
#define SCAN_B 1024
#define SCAN_NB ((N_NODES + SCAN_B - 1) / SCAN_B)   // 98

// -------- static device scratch (zero-initialized at module load) --------
__device__ __half g_y_src[(size_t)N_NODES * D];  // dinv_in[n] * (x @ (a*Ws)^T)[n]
__device__ __half g_y_dst[(size_t)N_NODES * D];  // dinv_out[n] * (x @ ((1-a)*Wd)^T)[n]
__device__ int   g_cnt_row[N_NODES], g_cnt_col[N_NODES];   // ALWAYS zero at call entry
__device__ int   g_off_row[N_NODES], g_off_col[N_NODES];
__device__ int   g_cur_row[N_NODES], g_cur_col[N_NODES];
__device__ int   g_part_row[SCAN_NB], g_part_col[SCAN_NB];
__device__ float g_dinv_out[N_NODES], g_dinv_in[N_NODES];
__device__ int   g_sorted_col[N_EDGES];
__device__ int   g_sorted_row[N_EDGES];

__device__ __forceinline__ void cp_async16(void* smem_dst, const void* gsrc) {
  unsigned sa = (unsigned)__cvta_generic_to_shared(smem_dst);
  asm volatile("cp.async.ca.shared.global [%0], [%1], 16;" :: "r"(sa), "l"(gsrc));
}
__device__ __forceinline__ unsigned f2tf32(float f) {
  unsigned t; asm("cvt.rna.tf32.f32 %0, %1;" : "=r"(t) : "f"(f));
  return t;
}
__device__ __forceinline__ void mma_tf32(float* c, unsigned a0, unsigned a1,
                                         unsigned a2, unsigned a3,
                                         unsigned b0, unsigned b1) {
  asm volatile(
    "mma.sync.aligned.m16n8k8.row.col.f32.tf32.tf32.f32 "
    "{%0,%1,%2,%3}, {%4,%5,%6,%7}, {%8,%9}, {%0,%1,%2,%3};"
    : "+f"(c[0]), "+f"(c[1]), "+f"(c[2]), "+f"(c[3])
    : "r"(a0), "r"(a1), "r"(a2), "r"(a3), "r"(b0), "r"(b1));
}

// Per-block dtype detection: thread 0 inspects first 16 values as int64
// (int32 data read as int64 is out of range w.p. ~1). Deterministic, L2-hot.
__device__ __forceinline__ int block_detect_is64(const void* ei, int* sh_flag) {
  if (threadIdx.x == 0) {
    const long long* p = (const long long*)ei;
    int ok = 1;
#pragma unroll
    for (int j = 0; j < 16; j++) {
      long long v = p[j];
      if (v < 0 || v >= N_NODES) ok = 0;
    }
    *sh_flag = ok;
  }
  __syncthreads();
  return *sh_flag;
}

// -------- 1: degree histograms, 2 edges/thread, self-detecting --------
__global__ void k_hist(const void* ei) {
  __shared__ int sh_is64;
  int is64 = block_detect_is64(ei, &sh_is64);
  long long t = (long long)blockIdx.x * blockDim.x + threadIdx.x;
  if (t >= N_EDGES / 2) return;
  int r0, r1, c0, c1;
  if (is64) {
    longlong2 rr = ((const longlong2*)ei)[t];
    longlong2 cc = ((const longlong2*)((const long long*)ei + N_EDGES))[t];
    r0 = (int)rr.x; r1 = (int)rr.y; c0 = (int)cc.x; c1 = (int)cc.y;
  } else {
    int2 rr = ((const int2*)ei)[t];
    int2 cc = ((const int2*)((const int*)ei + N_EDGES))[t];
    r0 = rr.x; r1 = rr.y; c0 = cc.x; c1 = cc.y;
  }
  atomicAdd(&g_cnt_row[r0], 1); atomicAdd(&g_cnt_row[r1], 1);
  atomicAdd(&g_cnt_col[c0], 1); atomicAdd(&g_cnt_col[c1], 1);
}

// -------- B: blockwise scan; cursors; dinv (stream 2) --------
__global__ void k_scan_blocks() {
  __shared__ int sh[SCAN_B];
  int b = blockIdx.x, t = threadIdx.x;
  int gi = b * SCAN_B + t;

  int v = (gi < N_NODES) ? g_cnt_row[gi] : 0;
  sh[t] = v; __syncthreads();
  for (int o = 1; o < SCAN_B; o <<= 1) {
    int x = (t >= o) ? sh[t - o] : 0;
    __syncthreads(); sh[t] += x; __syncthreads();
  }
  if (gi < N_NODES) {
    g_off_row[gi] = sh[t] - v; g_cur_row[gi] = sh[t] - v;
    g_dinv_out[gi] = v > 0 ? rsqrtf((float)v) : 0.f;
  }
  if (t == SCAN_B - 1) g_part_row[b] = sh[t];
  __syncthreads();

  v = (gi < N_NODES) ? g_cnt_col[gi] : 0;
  sh[t] = v; __syncthreads();
  for (int o = 1; o < SCAN_B; o <<= 1) {
    int x = (t >= o) ? sh[t - o] : 0;
    __syncthreads(); sh[t] += x; __syncthreads();
  }
  if (gi < N_NODES) {
    g_off_col[gi] = sh[t] - v; g_cur_col[gi] = sh[t] - v;
    g_dinv_in[gi] = v > 0 ? rsqrtf((float)v) : 0.f;
  }
  if (t == SCAN_B - 1) g_part_col[b] = sh[t];
}

__global__ void k_scan_tops() {
  __shared__ int sh[128];
  int t = threadIdx.x;
  int v = (t < SCAN_NB) ? g_part_row[t] : 0;
  sh[t] = v; __syncthreads();
  for (int o = 1; o < 128; o <<= 1) {
    int x = (t >= o) ? sh[t - o] : 0;
    __syncthreads(); sh[t] += x; __syncthreads();
  }
  if (t < SCAN_NB) g_part_row[t] = sh[t] - v;
  __syncthreads();
  v = (t < SCAN_NB) ? g_part_col[t] : 0;
  sh[t] = v; __syncthreads();
  for (int o = 1; o < 128; o <<= 1) {
    int x = (t >= o) ? sh[t - o] : 0;
    __syncthreads(); sh[t] += x; __syncthreads();
  }
  if (t < SCAN_NB) g_part_col[t] = sh[t] - v;
}

// -------- build CSR, 2 edges/thread, self-detecting --------
__global__ void k_build(const void* ei) {
  __shared__ int sh_is64;
  int is64 = block_detect_is64(ei, &sh_is64);
  long long t = (long long)blockIdx.x * blockDim.x + threadIdx.x;
  if (t >= N_EDGES / 2) return;
  int r0, r1, c0, c1;
  if (is64) {
    longlong2 rr = ((const longlong2*)ei)[t];
    longlong2 cc = ((const longlong2*)((const long long*)ei + N_EDGES))[t];
    r0 = (int)rr.x; r1 = (int)rr.y; c0 = (int)cc.x; c1 = (int)cc.y;
  } else {
    int2 rr = ((const int2*)ei)[t];
    int2 cc = ((const int2*)((const int*)ei + N_EDGES))[t];
    r0 = rr.x; r1 = rr.y; c0 = cc.x; c1 = cc.y;
  }
  int p0 = atomicAdd(&g_cur_row[r0], 1) + g_part_row[r0 >> 10];
  g_sorted_col[p0] = c0;
  int p1 = atomicAdd(&g_cur_row[r1], 1) + g_part_row[r1 >> 10];
  g_sorted_col[p1] = c1;
  int q0 = atomicAdd(&g_cur_col[c0], 1) + g_part_col[c0 >> 10];
  g_sorted_row[q0] = r0;
  int q1 = atomicAdd(&g_cur_col[c1], 1) + g_part_col[c1 >> 10];
  g_sorted_row[q1] = r1;
}

// -------- transform: tf32 mma, fp16 prescaled y (R13, frozen) --------
__global__ void __launch_bounds__(256, 1) k_transform(
    const float* __restrict__ x,
    const float* __restrict__ W_src,
    const float* __restrict__ W_dst) {
  extern __shared__ float smem[];
  float* Wsm = smem;
  float* xs0 = Wsm + 128 * NSTR;
  float* xs1 = xs0 + TILE_NODES * XSTR;

  int tid = threadIdx.x;
  for (int idx = tid; idx < 128 * 256; idx += 256) {
    int k = idx >> 8, n = idx & 255;
    float w = (n < 128) ? ALPHA * W_src[n * 128 + k]
                        : (1.f - ALPHA) * W_dst[(n - 128) * 128 + k];
    Wsm[k * NSTR + n] = __uint_as_float(f2tf32(w));
  }

  int lane = tid & 31, wid = tid >> 5;
  int g = lane >> 2, tig = lane & 3;
  int wm = wid & 1, wn = wid >> 1;

  {
    long long base = (long long)blockIdx.x * TILE_NODES;
    for (int i = tid; i < TILE_NODES * 32; i += 256) {
      int row = i >> 5, ch = i & 31;
      cp_async16(xs0 + row * XSTR + ch * 4, x + (base + row) * D + ch * 4);
    }
    asm volatile("cp.async.commit_group;");
  }

  int pp = 0;
  for (int tile = blockIdx.x; tile < N_TILES; tile += gridDim.x) {
    long long base = (long long)tile * TILE_NODES;
    float* xsr = pp ? xs1 : xs0;
    float* xsw = pp ? xs0 : xs1;

    asm volatile("cp.async.wait_group 0;");
    __syncthreads();

    int next = tile + gridDim.x;
    if (next < N_TILES) {
      long long nb = (long long)next * TILE_NODES;
      for (int i = tid; i < TILE_NODES * 32; i += 256) {
        int row = i >> 5, ch = i & 31;
        cp_async16(xsw + row * XSTR + ch * 4, x + (nb + row) * D + ch * 4);
      }
      asm volatile("cp.async.commit_group;");
    }

    float c[8][4];
#pragma unroll
    for (int nt = 0; nt < 8; nt++) { c[nt][0]=0.f; c[nt][1]=0.f; c[nt][2]=0.f; c[nt][3]=0.f; }

#pragma unroll
    for (int ks = 0; ks < 16; ks++) {
      int k0 = ks * 8;
      const float* ab = xsr + (wm * 16 + g) * XSTR + k0 + tig;
      unsigned a0 = f2tf32(ab[0]);
      unsigned a1 = f2tf32(ab[8 * XSTR]);
      unsigned a2 = f2tf32(ab[4]);
      unsigned a3 = f2tf32(ab[8 * XSTR + 4]);
      const float* bb = Wsm + (k0 + tig) * NSTR + wn * 64 + g;
#pragma unroll
      for (int nt = 0; nt < 8; nt++) {
        unsigned b0 = __float_as_uint(bb[nt * 8]);
        unsigned b1 = __float_as_uint(bb[nt * 8 + 4 * NSTR]);
        mma_tf32(c[nt], a0, a1, a2, a3, b0, b1);
      }
    }

    {
      int r0 = wm * 16 + g, r1 = r0 + 8;
      long long n0 = base + r0, n1 = base + r1;
      float s0, s1;
      __half* ybase;
      if (wn < 2) {
        int c0 = g_cnt_col[n0], c1 = g_cnt_col[n1];
        s0 = c0 > 0 ? rsqrtf((float)c0) : 0.f;
        s1 = c1 > 0 ? rsqrtf((float)c1) : 0.f;
        ybase = g_y_src;
      } else {
        int c0 = g_cnt_row[n0], c1 = g_cnt_row[n1];
        s0 = c0 > 0 ? rsqrtf((float)c0) : 0.f;
        s1 = c1 > 0 ? rsqrtf((float)c1) : 0.f;
        ybase = g_y_dst;
      }
      int cb = (wn & 1) * 64 + tig * 2;
#pragma unroll
      for (int nt = 0; nt < 8; nt++) {
        __half2 h0 = __floats2half2_rn(s0 * c[nt][0], s0 * c[nt][1]);
        *(__half2*)(ybase + n0 * D + cb + nt * 8) = h0;
        __half2 h1 = __floats2half2_rn(s1 * c[nt][2], s1 * c[nt][3]);
        *(__half2*)(ybase + n1 * D + cb + nt * 8) = h1;
      }
    }
    pp ^= 1;
  }
}

// -------- gather: warp/node, uint2 rows, 4-way MLP; clears counts in tail ----
__device__ __forceinline__ void acc_row(float4& acc, const uint2 v) {
  float2 v0 = __half22float2(*(const __half2*)&v.x);
  float2 v1 = __half22float2(*(const __half2*)&v.y);
  acc.x += v0.x; acc.y += v0.y; acc.z += v1.x; acc.w += v1.y;
}

__global__ void __launch_bounds__(256, 6) k_gather(
    float* __restrict__ out,
    const float* __restrict__ b_src, const float* __restrict__ b_dst) {
  int lane = threadIdx.x & 31;
  int node = (blockIdx.x * blockDim.x + threadIdx.x) >> 5;
  if (node >= N_NODES) return;

  float4 accf = make_float4(0.f, 0.f, 0.f, 0.f);
  float4 accb = make_float4(0.f, 0.f, 0.f, 0.f);
  const unsigned FULL = 0xffffffffu;
  int cnt_r = g_cnt_row[node];
  int cnt_c = g_cnt_col[node];

  {
    int s = g_off_row[node] + g_part_row[node >> 10];
    for (int bse = 0; bse < cnt_r; bse += 32) {
      int n = min(32, cnt_r - bse);
      int idx = (lane < n) ? g_sorted_col[s + bse + lane] : 0;
      int j = 0;
      for (; j + 4 <= n; j += 4) {
        int i0 = __shfl_sync(FULL, idx, j);
        int i1 = __shfl_sync(FULL, idx, j + 1);
        int i2 = __shfl_sync(FULL, idx, j + 2);
        int i3 = __shfl_sync(FULL, idx, j + 3);
        uint2 v0 = ((const uint2*)g_y_src)[(long long)i0 * 32 + lane];
        uint2 v1 = ((const uint2*)g_y_src)[(long long)i1 * 32 + lane];
        uint2 v2 = ((const uint2*)g_y_src)[(long long)i2 * 32 + lane];
        uint2 v3 = ((const uint2*)g_y_src)[(long long)i3 * 32 + lane];
        acc_row(accf, v0); acc_row(accf, v1); acc_row(accf, v2); acc_row(accf, v3);
      }
      for (; j < n; j++) {
        int i0 = __shfl_sync(FULL, idx, j);
        uint2 v0 = ((const uint2*)g_y_src)[(long long)i0 * 32 + lane];
        acc_row(accf, v0);
      }
    }
  }
  {
    int s = g_off_col[node] + g_part_col[node >> 10];
    for (int bse = 0; bse < cnt_c; bse += 32) {
      int n = min(32, cnt_c - bse);
      int idx = (lane < n) ? g_sorted_row[s + bse + lane] : 0;
      int j = 0;
      for (; j + 4 <= n; j += 4) {
        int i0 = __shfl_sync(FULL, idx, j);
        int i1 = __shfl_sync(FULL, idx, j + 1);
        int i2 = __shfl_sync(FULL, idx, j + 2);
        int i3 = __shfl_sync(FULL, idx, j + 3);
        uint2 v0 = ((const uint2*)g_y_dst)[(long long)i0 * 32 + lane];
        uint2 v1 = ((const uint2*)g_y_dst)[(long long)i1 * 32 + lane];
        uint2 v2 = ((const uint2*)g_y_dst)[(long long)i2 * 32 + lane];
        uint2 v3 = ((const uint2*)g_y_dst)[(long long)i3 * 32 + lane];
        acc_row(accb, v0); acc_row(accb, v1); acc_row(accb, v2); acc_row(accb, v3);
      }
      for (; j < n; j++) {
        int i0 = __shfl_sync(FULL, idx, j);
        uint2 v0 = ((const uint2*)g_y_dst)[(long long)i0 * 32 + lane];
        acc_row(accb, v0);
      }
    }
  }

  float dout = g_dinv_out[node];
  float di   = g_dinv_in[node];
  int bidx = lane * 4;
  float4 o;
  o.x = ALPHA * b_src[bidx+0] + (1.f-ALPHA) * b_dst[bidx+0] + dout * accf.x + di * accb.x;
  o.y = ALPHA * b_src[bidx+1] + (1.f-ALPHA) * b_dst[bidx+1] + dout * accf.y + di * accb.y;
  o.z = ALPHA * b_src[bidx+2] + (1.f-ALPHA) * b_dst[bidx+2] + dout * accf.z + di * accb.z;
  o.w = ALPHA * b_src[bidx+3] + (1.f-ALPHA) * b_dst[bidx+3] + dout * accf.w + di * accb.w;
  ((float4*)(out + (long long)node * D))[lane] = o;

  // restore the counts-zero invariant for the next graph replay
  // (transform + this warp are done with this node's counts; one warp per node)
  if (lane == 0) { g_cnt_row[node] = 0; g_cnt_col[node] = 0; }
}

// -------- launch: fork-join; no detect, no clear --------
extern "C" void kernel_launch(void* const* d_in, const int* in_sizes, int n_in,
                              void* d_out, int out_size) {
  const float* x     = (const float*)d_in[0];
  const void*  ei    = d_in[1];
  const float* W_src = (const float*)d_in[2];
  const float* b_src = (const float*)d_in[3];
  const float* W_dst = (const float*)d_in[4];
  const float* b_dst = (const float*)d_in[5];
  float* out = (float*)d_out;

  cudaStream_t s2;
  cudaStreamCreateWithFlags(&s2, cudaStreamNonBlocking);
  cudaEvent_t evFork, evJoin;
  cudaEventCreateWithFlags(&evFork, cudaEventDisableTiming);
  cudaEventCreateWithFlags(&evJoin, cudaEventDisableTiming);

  k_hist<<<(N_EDGES / 2 + 255) / 256, 256>>>(ei);

  cudaEventRecord(evFork, 0);
  cudaStreamWaitEvent(s2, evFork, 0);
  k_scan_blocks<<<SCAN_NB, SCAN_B, 0, s2>>>();
  k_scan_tops<<<1, 128, 0, s2>>>();
  k_build<<<(N_EDGES / 2 + 255) / 256, 256, 0, s2>>>(ei);
  cudaEventRecord(evJoin, s2);

  size_t smem_bytes = (size_t)(128 * NSTR + 2 * TILE_NODES * XSTR) * sizeof(float);
  cudaFuncSetAttribute(k_transform, cudaFuncAttributeMaxDynamicSharedMemorySize,
                       (int)smem_bytes);
  k_transform<<<152, 256, smem_bytes>>>(x, W_src, W_dst);

  cudaStreamWaitEvent(0, evJoin, 0);
  k_gather<<<(N_NODES * 32 + 255) / 256, 256>>>(out, b_src, b_dst);
}